// round 5
// baseline (speedup 1.0000x reference)
#include <cuda_runtime.h>
#include <mma.h>
#include <cstdint>

#define NODES 50000
#define MAXE  1600000
#define CE    64
#define CN    256
#define COUT  256
#define KSTEP 16
#define NKS   20   // 320 / 16
#define STAGES 3

#define AS_LD   20                    // 16 + 4 pad
#define BS_LD   264                   // 256 + 8 pad
#define AS_STAGE (128 * AS_LD)
#define BS_STAGE (16 * BS_LD)
#define SMEM_FLOATS (STAGES * AS_STAGE + STAGES * BS_STAGE)
#define SMEM_BYTES  (SMEM_FLOATS * 4) // 81,408 B

// __device__ scratch (no allocations)
__device__ float g_A[(size_t)NODES * CE];   // A/D, written fully by gather
__device__ float g_invD[NODES];
__device__ int   g_count[NODES];            // per-node edge count
__device__ int   g_fill[NODES];             // scan writes start; fill bumps to end
__device__ int   g_eid[MAXE];               // CSR edge ids

// ---------------------------------------------------------------------------
// cp.async helpers
// ---------------------------------------------------------------------------
__device__ __forceinline__ void cp_async16(void* smem, const void* gsrc, bool pred) {
    uint32_t s = (uint32_t)__cvta_generic_to_shared(smem);
    int sz = pred ? 16 : 0;
    asm volatile("cp.async.cg.shared.global [%0], [%1], 16, %2;\n"
                 :: "r"(s), "l"(gsrc), "r"(sz));
}
#define CP_COMMIT() asm volatile("cp.async.commit_group;\n" ::: "memory")
#define CP_WAIT(n)  asm volatile("cp.async.wait_group %0;\n" :: "n"(n) : "memory")

// ---------------------------------------------------------------------------
// 1) init: invD + zero counters
// ---------------------------------------------------------------------------
__global__ void init_kernel(const float* __restrict__ D, int nNodes) {
    int i = blockIdx.x * blockDim.x + threadIdx.x;
    if (i < nNodes) {
        g_invD[i]  = __frcp_rn(__ldg(D + i));
        g_count[i] = 0;
    }
}

// ---------------------------------------------------------------------------
// 2) histogram of destinations (integer red.add, no return)
// ---------------------------------------------------------------------------
__global__ void hist_kernel(const int* __restrict__ row_idx, int E) {
    int i = blockIdx.x * blockDim.x + threadIdx.x;
    if (i < E) atomicAdd(&g_count[__ldg(row_idx + i)], 1);
}

// ---------------------------------------------------------------------------
// 3) single-block exclusive scan of g_count -> g_fill (start offsets)
// ---------------------------------------------------------------------------
__global__ void scan_kernel(int nNodes) {
    __shared__ int sm[1024];
    const int t   = threadIdx.x;
    const int per = (nNodes + 1023) >> 10;
    const int base = t * per;

    int s = 0;
    for (int j = 0; j < per; j++) {
        int idx = base + j;
        if (idx < nNodes) s += g_count[idx];
    }
    sm[t] = s;
    __syncthreads();

    int v = s;
    for (int off = 1; off < 1024; off <<= 1) {
        int u = (t >= off) ? sm[t - off] : 0;
        __syncthreads();
        v += u;
        sm[t] = v;
        __syncthreads();
    }
    int run = v - s;   // exclusive prefix of this thread's chunk
    for (int j = 0; j < per; j++) {
        int idx = base + j;
        if (idx < nNodes) {
            g_fill[idx] = run;
            run += g_count[idx];
        }
    }
}

// ---------------------------------------------------------------------------
// 4) fill CSR: claim slot, write edge id
// ---------------------------------------------------------------------------
__global__ void fill_kernel(const int* __restrict__ row_idx, int E) {
    int i = blockIdx.x * blockDim.x + threadIdx.x;
    if (i < E) {
        int p = atomicAdd(&g_fill[__ldg(row_idx + i)], 1);
        g_eid[p] = i;
    }
}

// ---------------------------------------------------------------------------
// 5) gather: one warp per node; lane handles channels {lane, lane+32}
//    after fill, g_fill[n] == end offset; start = end - count.
// ---------------------------------------------------------------------------
__global__ void gather_kernel(const float* __restrict__ ea, int nNodes) {
    int w    = (blockIdx.x * blockDim.x + threadIdx.x) >> 5;
    int lane = threadIdx.x & 31;
    if (w >= nNodes) return;

    const int end   = g_fill[w];
    const int cnt   = g_count[w];
    const int start = end - cnt;

    float a0 = 0.f, a1 = 0.f;
    for (int j = start; j < end; j += 32) {
        int rem = end - j;
        int my  = (lane < rem) ? __ldg(g_eid + j + lane) : 0;
        if (rem >= 32) {
#pragma unroll
            for (int t = 0; t < 32; t++) {
                int eid = __shfl_sync(0xffffffffu, my, t);
                const float* row = ea + (size_t)eid * CE;
                a0 += __ldg(row + lane);
                a1 += __ldg(row + lane + 32);
            }
        } else {
            for (int t = 0; t < rem; t++) {
                int eid = __shfl_sync(0xffffffffu, my, t);
                const float* row = ea + (size_t)eid * CE;
                a0 += __ldg(row + lane);
                a1 += __ldg(row + lane + 32);
            }
        }
    }
    float inv = g_invD[w];
    g_A[(size_t)w * CE + lane]      = a0 * inv;
    g_A[(size_t)w * CE + lane + 32] = a1 * inv;
}

// ---------------------------------------------------------------------------
// 6) fused GEMM  out = relu([A/D | X] @ [W_pass; W_self] + bias)  (unchanged)
// ---------------------------------------------------------------------------
using namespace nvcuda;

__device__ __forceinline__ void load_stage(
    float* As, float* Bs, int ks, int row0, int nNodes,
    const float* __restrict__ X, const float* __restrict__ Wp,
    const float* __restrict__ Ws, int tid)
{
    const int k0 = ks * KSTEP;
    {
        int r  = tid >> 2, c4 = (tid & 3) * 4;
        int gr = row0 + r;
        bool ok = gr < nNodes;
        int grc = ok ? gr : 0;
        const float* src = (k0 < 64)
            ? (g_A + (size_t)grc * CE + (k0 + c4))
            : (X   + (size_t)grc * CN + (k0 - 64 + c4));
        cp_async16(As + r * AS_LD + c4, src, ok);
    }
#pragma unroll
    for (int i = 0; i < 2; i++) {
        int j = tid + i * 512;
        int r = j >> 6, c4 = (j & 63) * 4;
        int k = k0 + r;
        const float* src = (k < 64)
            ? (Wp + (size_t)k * COUT + c4)
            : (Ws + (size_t)(k - 64) * COUT + c4);
        cp_async16(Bs + r * BS_LD + c4, src, true);
    }
}

__global__ __launch_bounds__(512, 1)
void gemm_kernel(const float* __restrict__ X,
                 const float* __restrict__ Wp, const float* __restrict__ bp,
                 const float* __restrict__ Ws, const float* __restrict__ bs,
                 float* __restrict__ out, int nNodes) {
    extern __shared__ float smem[];
    float* AsBase = smem;
    float* BsBase = smem + STAGES * AS_STAGE;

    const int tid  = threadIdx.x;
    const int warp = tid >> 5;
    const int wm   = warp >> 2;
    const int wn   = warp & 3;
    const int row0 = blockIdx.x * 128;

    for (int i = tid; i < 16 * 256; i += 512) {
        int r = i >> 8, c = i & 255;
        BsBase[r * BS_LD + c] = __ldg(bp + c) + __ldg(bs + c);
    }
    __syncthreads();

    wmma::fragment<wmma::accumulator, 16, 16, 8, float> acc[2][4];
#pragma unroll
    for (int mi = 0; mi < 2; mi++)
#pragma unroll
        for (int ni = 0; ni < 4; ni++)
            wmma::load_matrix_sync(acc[mi][ni], BsBase + wn * 64 + ni * 16,
                                   BS_LD, wmma::mem_row_major);
    __syncthreads();

#pragma unroll
    for (int s = 0; s < STAGES; s++) {
        load_stage(AsBase + s * AS_STAGE, BsBase + s * BS_STAGE, s,
                   row0, nNodes, X, Wp, Ws, tid);
        CP_COMMIT();
    }

    for (int ks = 0; ks < NKS; ks++) {
        const int buf = ks % STAGES;
        float* As = AsBase + buf * AS_STAGE;
        float* Bs = BsBase + buf * BS_STAGE;
        CP_WAIT(STAGES - 1);
        __syncthreads();

#pragma unroll
        for (int kk8 = 0; kk8 < 2; kk8++) {
            wmma::fragment<wmma::matrix_a, 16, 16, 8, wmma::precision::tf32,
                           wmma::row_major> af[2];
            wmma::fragment<wmma::matrix_b, 16, 16, 8, wmma::precision::tf32,
                           wmma::row_major> bf[4];
#pragma unroll
            for (int mi = 0; mi < 2; mi++) {
                wmma::load_matrix_sync(af[mi],
                    As + (wm * 32 + mi * 16) * AS_LD + kk8 * 8, AS_LD);
#pragma unroll
                for (int t = 0; t < af[mi].num_elements; t++)
                    af[mi].x[t] = wmma::__float_to_tf32(af[mi].x[t]);
            }
#pragma unroll
            for (int ni = 0; ni < 4; ni++) {
                wmma::load_matrix_sync(bf[ni],
                    Bs + (kk8 * 8) * BS_LD + wn * 64 + ni * 16, BS_LD);
#pragma unroll
                for (int t = 0; t < bf[ni].num_elements; t++)
                    bf[ni].x[t] = wmma::__float_to_tf32(bf[ni].x[t]);
            }
#pragma unroll
            for (int mi = 0; mi < 2; mi++)
#pragma unroll
                for (int ni = 0; ni < 4; ni++)
                    wmma::mma_sync(acc[mi][ni], af[mi], bf[ni], acc[mi][ni]);
        }
        __syncthreads();

        if (ks + STAGES < NKS) {
            load_stage(As, Bs, ks + STAGES, row0, nNodes, X, Wp, Ws, tid);
            CP_COMMIT();
        }
    }

#pragma unroll
    for (int mi = 0; mi < 2; mi++)
#pragma unroll
        for (int ni = 0; ni < 4; ni++)
#pragma unroll
            for (int t = 0; t < acc[mi][ni].num_elements; t++)
                acc[mi][ni].x[t] = fmaxf(acc[mi][ni].x[t], 0.f);

    if (row0 + 128 <= nNodes) {
#pragma unroll
        for (int mi = 0; mi < 2; mi++)
#pragma unroll
            for (int ni = 0; ni < 4; ni++)
                wmma::store_matrix_sync(
                    out + (size_t)(row0 + wm * 32 + mi * 16) * COUT
                        + wn * 64 + ni * 16,
                    acc[mi][ni], COUT, wmma::mem_row_major);
    } else {
        float* stg = smem;
        for (int chunk = 0; chunk < 4; chunk++) {
            __syncthreads();
            if (wm == chunk) {
#pragma unroll
                for (int mi = 0; mi < 2; mi++)
#pragma unroll
                    for (int ni = 0; ni < 4; ni++)
                        wmma::store_matrix_sync(
                            stg + (mi * 16) * BS_LD + wn * 64 + ni * 16,
                            acc[mi][ni], BS_LD, wmma::mem_row_major);
            }
            __syncthreads();
            int base = row0 + chunk * 32;
            for (int idx = tid; idx < 32 * 256; idx += 512) {
                int r = idx >> 8, c = idx & 255;
                int gr = base + r;
                if (gr < nNodes)
                    out[(size_t)gr * COUT + c] = stg[r * BS_LD + c];
            }
        }
    }
}

// ---------------------------------------------------------------------------
extern "C" void kernel_launch(void* const* d_in, const int* in_sizes, int n_in,
                              void* d_out, int out_size) {
    const float* D   = (const float*)d_in[0];
    const int*   row = (const int*)d_in[1];
    const float* ea  = (const float*)d_in[2];
    const float* X   = (const float*)d_in[3];
    const float* Wp  = (const float*)d_in[4];
    const float* bp  = (const float*)d_in[5];
    const float* Ws  = (const float*)d_in[6];
    const float* bs  = (const float*)d_in[7];
    float* out = (float*)d_out;

    const int nNodes = in_sizes[0];
    const int E      = in_sizes[1];

    static bool attr_set = false;
    if (!attr_set) {
        cudaFuncSetAttribute(gemm_kernel,
                             cudaFuncAttributeMaxDynamicSharedMemorySize,
                             SMEM_BYTES);
        attr_set = true;
    }

    init_kernel<<<(nNodes + 255) / 256, 256>>>(D, nNodes);
    hist_kernel<<<(E + 255) / 256, 256>>>(row, E);
    scan_kernel<<<1, 1024>>>(nNodes);
    fill_kernel<<<(E + 255) / 256, 256>>>(row, E);
    gather_kernel<<<(nNodes * 32 + 255) / 256, 256>>>(ea, nNodes);

    int grid = (nNodes + 127) / 128;
    gemm_kernel<<<grid, 512, SMEM_BYTES>>>(X, Wp, bp, Ws, bs, out, nNodes);
}

// round 6
// speedup vs baseline: 1.2893x; 1.2893x over previous
#include <cuda_runtime.h>
#include <mma.h>
#include <cstdint>

#define NODES 50000
#define CE    64
#define CN    256
#define COUT  256
#define KSTEP 32
#define NKS   10   // 320 / 32
#define STAGES 3

#define AS_LD   36                    // 32 + 4 pad
#define BS_LD   264                   // 256 + 8 pad
#define AS_STAGE (128 * AS_LD)
#define BS_STAGE (32 * BS_LD)
#define SMEM_FLOATS (STAGES * AS_STAGE + STAGES * BS_STAGE)
#define SMEM_BYTES  (SMEM_FLOATS * 4) // 156,672 B

// scratch: pre-scaled accumulator A/D (12.8 MB) + invD — __device__ globals
__device__ float g_A[(size_t)NODES * CE];
__device__ float g_invD[NODES];

// ---------------------------------------------------------------------------
// cp.async helpers
// ---------------------------------------------------------------------------
__device__ __forceinline__ void cp_async16(void* smem, const void* gsrc, bool pred) {
    uint32_t s = (uint32_t)__cvta_generic_to_shared(smem);
    int sz = pred ? 16 : 0;
    asm volatile("cp.async.cg.shared.global [%0], [%1], 16, %2;\n"
                 :: "r"(s), "l"(gsrc), "r"(sz));
}
#define CP_COMMIT() asm volatile("cp.async.commit_group;\n" ::: "memory")
#define CP_WAIT(n)  asm volatile("cp.async.wait_group %0;\n" :: "n"(n) : "memory")

// ---------------------------------------------------------------------------
// Kernel 1: zero accumulator + precompute invD
// ---------------------------------------------------------------------------
__global__ void zero_kernel(const float* __restrict__ D) {
    int i = blockIdx.x * blockDim.x + threadIdx.x;
    if (i < NODES) g_invD[i] = __frcp_rn(__ldg(D + i));
    if (i < NODES * CE / 4)
        reinterpret_cast<float4*>(g_A)[i] = make_float4(0.f, 0.f, 0.f, 0.f);
}

// ---------------------------------------------------------------------------
// Kernel 2: edge scatter, pre-scaled by invD[dest].  (R4 version, unchanged)
// ---------------------------------------------------------------------------
__global__ void scatter_kernel(const float4* __restrict__ ea,
                               const int* __restrict__ row_idx,
                               int total16) {
    int i = blockIdx.x * 256 + threadIdx.x;
    if (i >= total16) return;
    int e = i >> 4;
    int t = i & 15;
    int r = __ldg(row_idx + e);
    float s = __ldg(g_invD + r);
    float4 v = __ldg(ea + i);
    v.x *= s; v.y *= s; v.z *= s; v.w *= s;
    float* dst = g_A + (size_t)r * CE + t * 4;
    asm volatile("red.global.add.v4.f32 [%0], {%1, %2, %3, %4};"
                 :: "l"(dst), "f"(v.x), "f"(v.y), "f"(v.z), "f"(v.w)
                 : "memory");
}

// ---------------------------------------------------------------------------
// Kernel 3: fused GEMM  out = relu([A/D | X] @ [W_pass; W_self] + bias)
//   M=50000, N=256, K=320.  CTA 128x256, KSTEP=32, NKS=10, true 3-stage
//   cp.async pipeline with ONE __syncthreads per iteration.
//   512 threads = 16 warps 4(M)x4(N); warp tile 32x64 (2x4 tf32 frags).
// ---------------------------------------------------------------------------
using namespace nvcuda;

__device__ __forceinline__ void load_stage(
    float* As, float* Bs, int ks, int row0, int nNodes,
    const float* __restrict__ X, const float* __restrict__ Wp,
    const float* __restrict__ Ws, int tid)
{
    const int k0 = ks * KSTEP;
    // As: 128 rows x 32 k  (1024 float4, 2 per thread)
#pragma unroll
    for (int i = 0; i < 2; i++) {
        int j  = tid + i * 512;
        int r  = j >> 3, c4 = (j & 7) * 4;
        int gr = row0 + r;
        bool ok = gr < nNodes;
        int grc = ok ? gr : 0;
        const float* src = (k0 < 64)
            ? (g_A + (size_t)grc * CE + (k0 + c4))
            : (X   + (size_t)grc * CN + (k0 - 64 + c4));
        cp_async16(As + r * AS_LD + c4, src, ok);
    }
    // Bs: 32 k-rows x 256 cols  (2048 float4, 4 per thread)
#pragma unroll
    for (int i = 0; i < 4; i++) {
        int j = tid + i * 512;
        int r = j >> 6, c4 = (j & 63) * 4;
        int k = k0 + r;
        const float* src = (k < 64)
            ? (Wp + (size_t)k * COUT + c4)
            : (Ws + (size_t)(k - 64) * COUT + c4);
        cp_async16(Bs + r * BS_LD + c4, src, true);
    }
}

__global__ __launch_bounds__(512, 1)
void gemm_kernel(const float* __restrict__ X,
                 const float* __restrict__ Wp, const float* __restrict__ bp,
                 const float* __restrict__ Ws, const float* __restrict__ bs,
                 float* __restrict__ out, int nNodes) {
    extern __shared__ float smem[];
    float* AsBase = smem;
    float* BsBase = smem + STAGES * AS_STAGE;

    const int tid  = threadIdx.x;
    const int warp = tid >> 5;
    const int wm   = warp >> 2;        // 0..3, 32 rows each
    const int wn   = warp & 3;         // 0..3, 64 cols each
    const int row0 = blockIdx.x * 128;

    // ---- bias (b_pass + b_self) via Bs stage 0 ----
    for (int i = tid; i < 16 * 256; i += 512) {
        int r = i >> 8, c = i & 255;
        BsBase[r * BS_LD + c] = __ldg(bp + c) + __ldg(bs + c);
    }
    __syncthreads();

    wmma::fragment<wmma::accumulator, 16, 16, 8, float> acc[2][4];
#pragma unroll
    for (int mi = 0; mi < 2; mi++)
#pragma unroll
        for (int ni = 0; ni < 4; ni++)
            wmma::load_matrix_sync(acc[mi][ni], BsBase + wn * 64 + ni * 16,
                                   BS_LD, wmma::mem_row_major);
    __syncthreads();

    // ---- prologue: fill stages 0..STAGES-2 ----
#pragma unroll
    for (int s = 0; s < STAGES - 1; s++) {
        load_stage(AsBase + s * AS_STAGE, BsBase + s * BS_STAGE, s,
                   row0, nNodes, X, Wp, Ws, tid);
        CP_COMMIT();
    }

    for (int ks = 0; ks < NKS; ks++) {
        const int cbuf = ks % STAGES;
        float* As = AsBase + cbuf * AS_STAGE;
        float* Bs = BsBase + cbuf * BS_STAGE;

        // groups outstanding at top: {ks .. min(ks+1, NKS-1)}
        if (ks < NKS - 1) { CP_WAIT(1); } else { CP_WAIT(0); }
        __syncthreads();   // also guarantees compute(ks-1) drained -> its buf reusable

        // issue load for ks+2 into buf (ks+2)%STAGES (== buf of ks-1)
        if (ks + STAGES - 1 < NKS) {
            const int wbuf = (ks + STAGES - 1) % STAGES;
            load_stage(AsBase + wbuf * AS_STAGE, BsBase + wbuf * BS_STAGE,
                       ks + STAGES - 1, row0, nNodes, X, Wp, Ws, tid);
            CP_COMMIT();
        }

#pragma unroll
        for (int kk8 = 0; kk8 < 4; kk8++) {
            wmma::fragment<wmma::matrix_a, 16, 16, 8, wmma::precision::tf32,
                           wmma::row_major> af[2];
            wmma::fragment<wmma::matrix_b, 16, 16, 8, wmma::precision::tf32,
                           wmma::row_major> bf[4];
#pragma unroll
            for (int mi = 0; mi < 2; mi++) {
                wmma::load_matrix_sync(af[mi],
                    As + (wm * 32 + mi * 16) * AS_LD + kk8 * 8, AS_LD);
#pragma unroll
                for (int t = 0; t < af[mi].num_elements; t++)
                    af[mi].x[t] = wmma::__float_to_tf32(af[mi].x[t]);
            }
#pragma unroll
            for (int ni = 0; ni < 4; ni++) {
                wmma::load_matrix_sync(bf[ni],
                    Bs + (kk8 * 8) * BS_LD + wn * 64 + ni * 16, BS_LD);
#pragma unroll
                for (int t = 0; t < bf[ni].num_elements; t++)
                    bf[ni].x[t] = wmma::__float_to_tf32(bf[ni].x[t]);
            }
#pragma unroll
            for (int mi = 0; mi < 2; mi++)
#pragma unroll
                for (int ni = 0; ni < 4; ni++)
                    wmma::mma_sync(acc[mi][ni], af[mi], bf[ni], acc[mi][ni]);
        }
    }

    // ---- ReLU ----
#pragma unroll
    for (int mi = 0; mi < 2; mi++)
#pragma unroll
        for (int ni = 0; ni < 4; ni++)
#pragma unroll
            for (int t = 0; t < acc[mi][ni].num_elements; t++)
                acc[mi][ni].x[t] = fmaxf(acc[mi][ni].x[t], 0.f);

    __syncthreads();   // all compute done before smem reuse in tail path

    if (row0 + 128 <= nNodes) {
#pragma unroll
        for (int mi = 0; mi < 2; mi++)
#pragma unroll
            for (int ni = 0; ni < 4; ni++)
                wmma::store_matrix_sync(
                    out + (size_t)(row0 + wm * 32 + mi * 16) * COUT
                        + wn * 64 + ni * 16,
                    acc[mi][ni], COUT, wmma::mem_row_major);
    } else {
        float* stg = smem;   // 32 x BS_LD staging
        for (int chunk = 0; chunk < 4; chunk++) {
            __syncthreads();
            if (wm == chunk) {
#pragma unroll
                for (int mi = 0; mi < 2; mi++)
#pragma unroll
                    for (int ni = 0; ni < 4; ni++)
                        wmma::store_matrix_sync(
                            stg + (mi * 16) * BS_LD + wn * 64 + ni * 16,
                            acc[mi][ni], BS_LD, wmma::mem_row_major);
            }
            __syncthreads();
            int base = row0 + chunk * 32;
            for (int idx = tid; idx < 32 * 256; idx += 512) {
                int r = idx >> 8, c = idx & 255;
                int gr = base + r;
                if (gr < nNodes)
                    out[(size_t)gr * COUT + c] = stg[r * BS_LD + c];
            }
        }
    }
}

// ---------------------------------------------------------------------------
extern "C" void kernel_launch(void* const* d_in, const int* in_sizes, int n_in,
                              void* d_out, int out_size) {
    const float*  D   = (const float*)d_in[0];
    const int*    row = (const int*)d_in[1];
    const float4* ea  = (const float4*)d_in[2];
    const float*  X   = (const float*)d_in[3];
    const float*  Wp  = (const float*)d_in[4];
    const float*  bp  = (const float*)d_in[5];
    const float*  Ws  = (const float*)d_in[6];
    const float*  bs  = (const float*)d_in[7];
    float* out = (float*)d_out;

    const int nNodes = in_sizes[0];
    const int E      = in_sizes[1];

    static bool attr_set = false;
    if (!attr_set) {
        cudaFuncSetAttribute(gemm_kernel,
                             cudaFuncAttributeMaxDynamicSharedMemorySize,
                             SMEM_BYTES);
        attr_set = true;
    }

    // 1) zero accumulator + invD
    {
        int n4 = NODES * CE / 4;
        zero_kernel<<<(n4 + 255) / 256, 256>>>(D);
    }
    // 2) scatter edges (pre-scaled by invD)
    {
        int total16 = E * 16;
        scatter_kernel<<<(total16 + 255) / 256, 256>>>(ea, row, total16);
    }
    // 3) fused GEMM + bias + ReLU
    {
        int grid = (nNodes + 127) / 128;
        gemm_kernel<<<grid, 512, SMEM_BYTES>>>(X, Wp, bp, Ws, bs, out, nNodes);
    }
}